// round 2
// baseline (speedup 1.0000x reference)
#include <cuda_runtime.h>
#include <cuda_bf16.h>
#include <math.h>

// ContrastLoss: feat [4,64,512,512] f32, gt [4,19,512,512] i32 -> scalar f32
//
// loss = -(1/num_pos) * sum_{b,k,h,w} mask * logsoftmax_k( (k0n[k] . fn[:,p]) / tau )
// where k0[k,c] = sum_p mask[k,p] feat[c,p], k0n row-normalized, fn channel-normalized.

#define NPIX  (4 * 262144)   // b * h * w
#define HW    262144
#define KCLS  19
#define CCH   64
#define TAUF  0.07f

// -------- device scratch (no allocations allowed) --------
__device__ float          g_k0[KCLS * CCH];
__device__ float2         g_k0n2[KCLS * 32];      // packed channel pairs
__device__ unsigned       g_maskbuf[NPIX];        // 19-bit class mask per pixel
__device__ int            g_numpos;
__device__ double         g_loss;

// -------- f32x2 helpers --------
__device__ __forceinline__ unsigned long long pack2(float a, float b) {
    unsigned long long r;
    asm("mov.b64 %0, {%1, %2};" : "=l"(r) : "f"(a), "f"(b));
    return r;
}
__device__ __forceinline__ void unpack2(unsigned long long v, float& a, float& b) {
    asm("mov.b64 {%0, %1}, %2;" : "=f"(a), "=f"(b) : "l"(v));
}
__device__ __forceinline__ void ffma2(unsigned long long& d, unsigned long long a,
                                      unsigned long long b) {
    asm("fma.rn.f32x2 %0, %1, %2, %0;" : "+l"(d) : "l"(a), "l"(b));
}

// -------- kernel 0: zero accumulators (runs every graph replay) --------
__global__ void k_zero() {
    int t = blockIdx.x * 256 + threadIdx.x;
    if (t < KCLS * CCH) g_k0[t] = 0.f;
    if (t == 0) { g_numpos = 0; g_loss = 0.0; }
}

// -------- kernel 1: prototype scatter-sum + mask packing --------
// Block = 256 threads. Thread j owns channel c = j>>2 and pixel-quarter q = j&3.
// Tile = 1024 pixels. Masks staged to shared (and saved to g_maskbuf for pass 2).
__global__ __launch_bounds__(256) void k_proto(const float* __restrict__ feat,
                                               const int* __restrict__ gt) {
    __shared__ unsigned smask[1024];
    const int j = threadIdx.x;
    const int c = j >> 2;
    const int q = j & 3;

    float acc[KCLS];
#pragma unroll
    for (int k = 0; k < KCLS; k++) acc[k] = 0.f;
    int cnt = 0;

    for (int tile = blockIdx.x * 1024; tile < NPIX; tile += gridDim.x * 1024) {
        const int b  = tile >> 18;
        const int hw = tile & (HW - 1);

        // --- stage: 4 consecutive pixels per thread, build 19-bit mask words ---
        {
            const int p = hw + 4 * j;
            unsigned m0 = 0, m1 = 0, m2 = 0, m3 = 0;
#pragma unroll
            for (int k = 0; k < KCLS; k++) {
                const int4 g = *reinterpret_cast<const int4*>(
                    gt + (size_t)(b * KCLS + k) * HW + p);
                m0 |= (unsigned)(g.x == 1) << k;
                m1 |= (unsigned)(g.y == 1) << k;
                m2 |= (unsigned)(g.z == 1) << k;
                m3 |= (unsigned)(g.w == 1) << k;
            }
            const uint4 mv = make_uint4(m0, m1, m2, m3);
            *reinterpret_cast<uint4*>(&smask[4 * j]) = mv;
            *reinterpret_cast<uint4*>(&g_maskbuf[tile + 4 * j]) = mv;
            cnt += __popc(m0) + __popc(m1) + __popc(m2) + __popc(m3);
        }
        __syncthreads();

        // --- accumulate: this thread's channel over its 256-pixel quarter ---
        const float* fb = feat + (size_t)(b * CCH + c) * HW + hw + q * 256;
#pragma unroll 2
        for (int t = 0; t < 64; t++) {
            const float4 f4 = *reinterpret_cast<const float4*>(fb + 4 * t);
            const uint4  m4 = *reinterpret_cast<const uint4*>(&smask[q * 256 + 4 * t]);
#pragma unroll
            for (int k = 0; k < KCLS; k++) {
                const unsigned bit = 1u << k;
                if (m4.x & bit) acc[k] += f4.x;
                if (m4.y & bit) acc[k] += f4.y;
                if (m4.z & bit) acc[k] += f4.z;
                if (m4.w & bit) acc[k] += f4.w;
            }
        }
        __syncthreads();
    }

#pragma unroll
    for (int k = 0; k < KCLS; k++) atomicAdd(&g_k0[k * CCH + c], acc[k]);
    atomicAdd(&g_numpos, cnt);
}

// -------- kernel 2: normalize prototypes, repack as channel pairs --------
// One block, 19 warps; warp k reduces its 64-channel norm.
__global__ void k_norm() {
    const int k    = threadIdx.x >> 5;
    const int lane = threadIdx.x & 31;
    if (k >= KCLS) return;
    const float v0 = g_k0[k * CCH + lane];
    const float v1 = g_k0[k * CCH + 32 + lane];
    float s = v0 * v0 + v1 * v1;
#pragma unroll
    for (int o = 16; o; o >>= 1) s += __shfl_xor_sync(0xffffffffu, s, o);
    const float inv = 1.f / fmaxf(sqrtf(s), 1e-12f);
    const float a = g_k0[k * CCH + 2 * lane]     * inv;
    const float b = g_k0[k * CCH + 2 * lane + 1] * inv;
    g_k0n2[k * 32 + lane] = make_float2(a, b);
}

// -------- kernel 3: per-pixel logits + log-softmax NLL, f32x2 mainloop --------
__global__ __launch_bounds__(256) void k_loss(const float* __restrict__ feat) {
    __shared__ float2 skn[KCLS * 32];
    for (int t = threadIdx.x; t < KCLS * 32; t += 256) skn[t] = g_k0n2[t];
    __syncthreads();

    float lsum = 0.f;
    for (int p = blockIdx.x * 256 + threadIdx.x; p < NPIX; p += gridDim.x * 256) {
        const unsigned m  = g_maskbuf[p];
        const int      b  = p >> 18;
        const int      hw = p & (HW - 1);
        const float* fb = feat + (size_t)(b * CCH) * HW + hw;

        unsigned long long d2[KCLS];
#pragma unroll
        for (int k = 0; k < KCLS; k++) d2[k] = 0ull;
        unsigned long long ss2 = 0ull;

#pragma unroll 4
        for (int c2 = 0; c2 < 32; c2++) {
            const float f0 = fb[(size_t)(2 * c2) * HW];
            const float f1 = fb[(size_t)(2 * c2 + 1) * HW];
            const unsigned long long f2 = pack2(f0, f1);
            ffma2(ss2, f2, f2);
#pragma unroll
            for (int k = 0; k < KCLS; k++) {
                const unsigned long long kn2 =
                    *reinterpret_cast<const unsigned long long*>(&skn[k * 32 + c2]);
                ffma2(d2[k], kn2, f2);
            }
        }

        float s0, s1;
        unpack2(ss2, s0, s1);
        const float sc = 1.f / (fmaxf(sqrtf(s0 + s1), 1e-12f) * TAUF);

        float l[KCLS];
        float mx = -1e30f;
#pragma unroll
        for (int k = 0; k < KCLS; k++) {
            float a, bq;
            unpack2(d2[k], a, bq);
            l[k] = (a + bq) * sc;
            mx = fmaxf(mx, l[k]);
        }
        float se = 0.f, sl = 0.f;
#pragma unroll
        for (int k = 0; k < KCLS; k++) {
            se += exp2f((l[k] - mx) * 1.4426950408889634f);
            if (m & (1u << k)) sl += l[k];
        }
        const float lse = mx + logf(se);
        lsum += (float)__popc(m) * lse - sl;
    }

    // block reduction -> double atomic
#pragma unroll
    for (int o = 16; o; o >>= 1) lsum += __shfl_xor_sync(0xffffffffu, lsum, o);
    __shared__ float wsum[8];
    if ((threadIdx.x & 31) == 0) wsum[threadIdx.x >> 5] = lsum;
    __syncthreads();
    if (threadIdx.x < 8) {
        float v = wsum[threadIdx.x];
#pragma unroll
        for (int o = 4; o; o >>= 1) v += __shfl_xor_sync(0x000000ffu, v, o);
        if (threadIdx.x == 0) atomicAdd(&g_loss, (double)v);
    }
}

// -------- kernel 4: finalize --------
__global__ void k_fin(float* out) {
    const int np = g_numpos;
    out[0] = (float)(g_loss / (double)(np > 0 ? np : 1));
}

extern "C" void kernel_launch(void* const* d_in, const int* in_sizes, int n_in,
                              void* d_out, int out_size) {
    const float* feat = (const float*)d_in[0];
    const int*   gt   = (const int*)d_in[1];
    float*       out  = (float*)d_out;

    k_zero <<<5, 256>>>();
    k_proto<<<592, 256>>>(feat, gt);
    k_norm <<<1, KCLS * 32>>>();
    k_loss <<<1184, 256>>>(feat);
    k_fin  <<<1, 1>>>(out);
}